// round 7
// baseline (speedup 1.0000x reference)
#include <cuda_runtime.h>
#include <math.h>

#define FIN 512
#define HD  16
#define CD  7
#define NMAX 100000
#define EMAX 3200000
#define TPB  256

typedef unsigned long long u64;

// ---------------- scratch (static device globals) ----------------
__device__ int   g_cnt [NMAX];        // in-degree (w/o self-loop); re-zeroed in scan
__device__ int   g_rows[NMAX + 1];    // CSR row starts (+ total at [n])
__device__ int   g_cur [NMAX];        // fill cursor
__device__ int   g_bsum[128];         // scan block sums
__device__ float g_dinv[NMAX];
__device__ int   g_esrc[EMAX];        // CSR: source node per edge slot
__device__ float g_h1  [NMAX * HD];
__device__ float g_h2  [NMAX * 8];    // 7 classes padded to 8 (col7 == 0)
__device__ int   g_barcnt;            // global barrier arrive counter
__device__ volatile int g_barphase;   // global barrier release phase
__device__ int   g_done;              // exit counter (self-reset)

// ---------------- f32x2 helpers ----------------
__device__ __forceinline__ u64 pk2(float lo, float hi) {
    u64 r; asm("mov.b64 %0, {%1, %2};" : "=l"(r) : "f"(lo), "f"(hi)); return r;
}
__device__ __forceinline__ void upk2(float& lo, float& hi, u64 v) {
    asm("mov.b64 {%0, %1}, %2;" : "=f"(lo), "=f"(hi) : "l"(v));
}
__device__ __forceinline__ void fma2(u64& d, u64 a, u64 b) {
    asm("fma.rn.f32x2 %0, %1, %2, %0;" : "+l"(d) : "l"(a), "l"(b));
}

// ---------------- global spin barrier (all blocks resident) ----------------
__device__ __forceinline__ void gbar(int target) {
    __syncthreads();
    if (threadIdx.x == 0) {
        __threadfence();
        if (atomicAdd(&g_barcnt, 1) == (int)gridDim.x - 1) {
            g_barcnt = 0;
            __threadfence();
            g_barphase = target;
        } else {
            while (g_barphase < target) { }
        }
        __threadfence();
    }
    __syncthreads();
}

// ---------------- GEMM1 tile: h1[tile] = x[tile] @ W1 ----------------
// 256 threads -> 256 nodes x 16 cols, 16-k subtiles. Thread (ng=t>>2, jg=t&3)
// owns nodes ng*4..+3 x cols jg*4..+3 as f32x2 node-pairs. Sync-before-write
// so consecutive tiles on one block are race-free.
__device__ __forceinline__ void gemm1_tile(const float* __restrict__ x,
                                           const float* __restrict__ W1,
                                           int n, int bid, unsigned char* smraw) {
    float4* sW4 = (float4*)smraw;                 // 16 k x 16 j  (1KB)
    float*  sXT = (float*)(smraw + 1024);         // k-major [k][node], stride 260

    const int t  = threadIdx.x;
    const int n0 = bid * 256;
    const int ng = t >> 2;
    const int jg = t & 3;

    u64 acc[2][4];
#pragma unroll
    for (int p = 0; p < 2; p++)
#pragma unroll
        for (int c = 0; c < 4; c++) acc[p][c] = 0ull;

    float4 rx[4];
    float4 rw = make_float4(0.f, 0.f, 0.f, 0.f);

    // prologue: stage subtile k0=0
    if (t < 64) rw = *(const float4*)(W1 + (size_t)(t >> 2) * HD + (t & 3) * 4);
#pragma unroll
    for (int i = 0; i < 4; i++) {
        int f = t + 256 * i;
        int node = n0 + (f >> 2);
        int kq = f & 3;
        rx[i] = (node < n) ? *(const float4*)(x + (size_t)node * FIN + kq * 4)
                           : make_float4(0.f, 0.f, 0.f, 0.f);
    }

#pragma unroll 1
    for (int k0 = 0; k0 < FIN; k0 += 16) {
        __syncthreads();   // protects smem from previous subtile/tile readers
        if (t < 64) sW4[t] = rw;
#pragma unroll
        for (int i = 0; i < 4; i++) {
            int f = t + 256 * i;
            int nl = f >> 2;
            int kq = f & 3;
            float* sp = &sXT[(kq * 4) * 260 + nl];
            sp[0]   = rx[i].x;
            sp[260] = rx[i].y;
            sp[520] = rx[i].z;
            sp[780] = rx[i].w;
        }
        __syncthreads();
        bool more = (k0 + 16 < FIN);
        if (more) {   // prefetch next subtile while computing
            if (t < 64)
                rw = *(const float4*)(W1 + (size_t)(k0 + 16 + (t >> 2)) * HD + (t & 3) * 4);
#pragma unroll
            for (int i = 0; i < 4; i++) {
                int f = t + 256 * i;
                int node = n0 + (f >> 2);
                int kq = f & 3;
                rx[i] = (node < n)
                      ? *(const float4*)(x + (size_t)node * FIN + k0 + 16 + kq * 4)
                      : make_float4(0.f, 0.f, 0.f, 0.f);
            }
        }
#pragma unroll
        for (int k = 0; k < 16; k++) {
            const float* xb = &sXT[k * 260 + ng * 4];
            u64 x01 = *(const u64*)xb;
            u64 x23 = *(const u64*)(xb + 2);
            float4 wv = sW4[k * 4 + jg];
            u64 w0 = pk2(wv.x, wv.x);
            u64 w1 = pk2(wv.y, wv.y);
            u64 w2 = pk2(wv.z, wv.z);
            u64 w3 = pk2(wv.w, wv.w);
            fma2(acc[0][0], x01, w0); fma2(acc[1][0], x23, w0);
            fma2(acc[0][1], x01, w1); fma2(acc[1][1], x23, w1);
            fma2(acc[0][2], x01, w2); fma2(acc[1][2], x23, w2);
            fma2(acc[0][3], x01, w3); fma2(acc[1][3], x23, w3);
        }
    }

#pragma unroll
    for (int p = 0; p < 2; p++) {
        float lo[4], hi[4];
#pragma unroll
        for (int c = 0; c < 4; c++) upk2(lo[c], hi[c], acc[p][c]);
        int node0 = n0 + ng * 4 + p * 2;
        if (node0 < n)
            *(float4*)&g_h1[(size_t)node0 * HD + jg * 4] =
                make_float4(lo[0], lo[1], lo[2], lo[3]);
        if (node0 + 1 < n)
            *(float4*)&g_h1[(size_t)(node0 + 1) * HD + jg * 4] =
                make_float4(hi[0], hi[1], hi[2], hi[3]);
    }
}

// ---------------- the one persistent kernel ----------------
// Grid MUST be fully resident: 444 = 148 SMs x 3 CTAs (launch_bounds(256,3)).

__global__ __launch_bounds__(TPB, 3) void k_fused(
    const float* __restrict__ x,
    const int*   __restrict__ src,
    const int*   __restrict__ dst,
    int e,
    const float* __restrict__ W1,
    const float* __restrict__ b1,
    const float* __restrict__ W2,
    const float* __restrict__ b2,
    float* __restrict__ out,
    int n)
{
    __shared__ __align__(16) unsigned char smraw[1024 + 16 * 260 * 4];
    const int t  = threadIdx.x;
    const int b  = blockIdx.x;
    const int G  = gridDim.x;
    const int nTiles = (n + 255) / 256;
    const int nbScan = (n + 1023) / 1024;

    // ================= Phase A: GEMM1 + degree count =================
    for (int bid = b; bid < nTiles; bid += G)
        gemm1_tile(x, W1, n, bid, smraw);
    for (int i = b * TPB + t; i < e; i += G * TPB)
        atomicAdd(&g_cnt[dst[i]], 1);
    gbar(1);

    // ================= Phase B: scan (3 sub-steps) =================
    int v0 = 0, v1 = 0, v2 = 0, v3 = 0, excl = 0, base = 0;
    if (b < nbScan) {
        int* s = (int*)smraw;
        base = b * 1024 + t * 4;
        v0 = (base + 0 < n) ? g_cnt[base + 0] : 0;
        v1 = (base + 1 < n) ? g_cnt[base + 1] : 0;
        v2 = (base + 2 < n) ? g_cnt[base + 2] : 0;
        v3 = (base + 3 < n) ? g_cnt[base + 3] : 0;
        if (base + 0 < n) g_dinv[base + 0] = rsqrtf((float)(v0 + 1));
        if (base + 1 < n) g_dinv[base + 1] = rsqrtf((float)(v1 + 1));
        if (base + 2 < n) g_dinv[base + 2] = rsqrtf((float)(v2 + 1));
        if (base + 3 < n) g_dinv[base + 3] = rsqrtf((float)(v3 + 1));
        int ts = v0 + v1 + v2 + v3;
        s[t] = ts;
        __syncthreads();
#pragma unroll
        for (int off = 1; off < 256; off <<= 1) {
            int xv = (t >= off) ? s[t - off] : 0;
            __syncthreads();
            s[t] += xv;
            __syncthreads();
        }
        excl = s[t] - ts;
        if (t == 255) g_bsum[b] = s[255];
    }
    gbar(2);

    if (b == 0) {   // parallel scan of block sums in smem
        int* s = (int*)smraw;
        int v = (t < nbScan) ? g_bsum[t] : 0;
        s[t] = v;
        __syncthreads();
#pragma unroll
        for (int off = 1; off < 256; off <<= 1) {
            int xv = (t >= off) ? s[t - off] : 0;
            __syncthreads();
            s[t] += xv;
            __syncthreads();
        }
        if (t < nbScan) g_bsum[t] = s[t] - v;   // exclusive
        if (t == 255)   g_rows[n] = s[255];     // total edges
    }
    gbar(3);

    if (b < nbScan) {
        int off = g_bsum[b];
        int r = excl + off;
        if (base + 0 < n) { g_rows[base + 0] = r; g_cur[base + 0] = r; g_cnt[base + 0] = 0; r += v0; }
        if (base + 1 < n) { g_rows[base + 1] = r; g_cur[base + 1] = r; g_cnt[base + 1] = 0; r += v1; }
        if (base + 2 < n) { g_rows[base + 2] = r; g_cur[base + 2] = r; g_cnt[base + 2] = 0; r += v2; }
        if (base + 3 < n) { g_rows[base + 3] = r; g_cur[base + 3] = r; g_cnt[base + 3] = 0; }
    }
    gbar(4);

    // ================= Phase C: CSR fill =================
    for (int i = b * TPB + t; i < e; i += G * TPB) {
        int s2 = src[i], d = dst[i];
        int pos = atomicAdd(&g_cur[d], 1);
        g_esrc[pos] = s2;
    }
    gbar(5);

    // ================= Phase D: agg layer 1 + layer-2 transform =================
    {
        float* sW2 = (float*)smraw;          // 16 x 8
        float* sb1 = (float*)(smraw + 512);  // 16
        if (t < HD * 8) {
            int j = t >> 3, cc = t & 7;
            sW2[t] = (cc < CD) ? W2[j * CD + cc] : 0.f;
        } else if (t < HD * 8 + HD) {
            sb1[t - HD * 8] = b1[t - HD * 8];
        }
        __syncthreads();

        const int nG1 = (n + 63) / 64;
        int c = t & 3;
        for (int g = b; g < nG1; g += G) {
            int node = g * 64 + (t >> 2);
            bool valid = node < n;
            if (!valid) node = n - 1;

            float dv = g_dinv[node];
            float4 h = *(const float4*)(g_h1 + (size_t)node * HD + c * 4);
            float4 acc = make_float4(h.x * dv, h.y * dv, h.z * dv, h.w * dv);

            int st = g_rows[node];
            int cnt = g_rows[node + 1] - st;
            int j = 0;
            for (; j + 1 < cnt; j += 2) {
                int s0 = g_esrc[st + j], s1 = g_esrc[st + j + 1];
                float m0 = g_dinv[s0],   m1 = g_dinv[s1];
                float4 w0 = *(const float4*)(g_h1 + (size_t)s0 * HD + c * 4);
                float4 w1 = *(const float4*)(g_h1 + (size_t)s1 * HD + c * 4);
                acc.x += w0.x * m0 + w1.x * m1;
                acc.y += w0.y * m0 + w1.y * m1;
                acc.z += w0.z * m0 + w1.z * m1;
                acc.w += w0.w * m0 + w1.w * m1;
            }
            if (j < cnt) {
                int s0 = g_esrc[st + j];
                float m0 = g_dinv[s0];
                float4 w0 = *(const float4*)(g_h1 + (size_t)s0 * HD + c * 4);
                acc.x += w0.x * m0; acc.y += w0.y * m0;
                acc.z += w0.z * m0; acc.w += w0.w * m0;
            }

            float q0 = fmaxf(acc.x * dv + sb1[c * 4 + 0], 0.f);
            float q1 = fmaxf(acc.y * dv + sb1[c * 4 + 1], 0.f);
            float q2 = fmaxf(acc.z * dv + sb1[c * 4 + 2], 0.f);
            float q3 = fmaxf(acc.w * dv + sb1[c * 4 + 3], 0.f);

            float p[8];
#pragma unroll
            for (int cc = 0; cc < 8; cc++) {
                p[cc] = q0 * sW2[(c * 4 + 0) * 8 + cc]
                      + q1 * sW2[(c * 4 + 1) * 8 + cc]
                      + q2 * sW2[(c * 4 + 2) * 8 + cc]
                      + q3 * sW2[(c * 4 + 3) * 8 + cc];
            }
#pragma unroll
            for (int cc = 0; cc < 8; cc++) {
                p[cc] += __shfl_xor_sync(0xFFFFFFFFu, p[cc], 1);
                p[cc] += __shfl_xor_sync(0xFFFFFFFFu, p[cc], 2);
            }
            if (valid) {
                if (c == 0)
                    *(float4*)(g_h2 + (size_t)node * 8)     = make_float4(p[0], p[1], p[2], p[3]);
                else if (c == 1)
                    *(float4*)(g_h2 + (size_t)node * 8 + 4) = make_float4(p[4], p[5], p[6], 0.f);
            }
        }
    }
    gbar(6);

    // ================= Phase E: agg layer 2 + bias + log_softmax =================
    {
        float* sb2 = (float*)smraw;
        if (t < 8) sb2[t] = (t < CD) ? b2[t] : -1e30f;   // pad lane -> exp()==0
        __syncthreads();

        const int nG2 = (n + 127) / 128;
        int c = t & 1;
        for (int g = b; g < nG2; g += G) {
            int node = g * 128 + (t >> 1);
            bool valid = node < n;
            if (!valid) node = n - 1;

            float dv = g_dinv[node];
            float4 h = *(const float4*)(g_h2 + (size_t)node * 8 + c * 4);
            float4 acc = make_float4(h.x * dv, h.y * dv, h.z * dv, h.w * dv);

            int st = g_rows[node];
            int cnt = g_rows[node + 1] - st;
            int j = 0;
            for (; j + 1 < cnt; j += 2) {
                int s0 = g_esrc[st + j], s1 = g_esrc[st + j + 1];
                float m0 = g_dinv[s0],   m1 = g_dinv[s1];
                float4 w0 = *(const float4*)(g_h2 + (size_t)s0 * 8 + c * 4);
                float4 w1 = *(const float4*)(g_h2 + (size_t)s1 * 8 + c * 4);
                acc.x += w0.x * m0 + w1.x * m1;
                acc.y += w0.y * m0 + w1.y * m1;
                acc.z += w0.z * m0 + w1.z * m1;
                acc.w += w0.w * m0 + w1.w * m1;
            }
            if (j < cnt) {
                int s0 = g_esrc[st + j];
                float m0 = g_dinv[s0];
                float4 w0 = *(const float4*)(g_h2 + (size_t)s0 * 8 + c * 4);
                acc.x += w0.x * m0; acc.y += w0.y * m0;
                acc.z += w0.z * m0; acc.w += w0.w * m0;
            }

            float o0 = acc.x * dv + sb2[c * 4 + 0];
            float o1 = acc.y * dv + sb2[c * 4 + 1];
            float o2 = acc.z * dv + sb2[c * 4 + 2];
            float o3 = acc.w * dv + sb2[c * 4 + 3];

            float m = fmaxf(fmaxf(o0, o1), fmaxf(o2, o3));
            m = fmaxf(m, __shfl_xor_sync(0xFFFFFFFFu, m, 1));
            float s = expf(o0 - m) + expf(o1 - m) + expf(o2 - m) + expf(o3 - m);
            s += __shfl_xor_sync(0xFFFFFFFFu, s, 1);
            float l = m + logf(s);

            if (valid) {
                float* op = out + (size_t)node * CD + c * 4;
                op[0] = o0 - l; op[1] = o1 - l; op[2] = o2 - l;
                if (c == 0) op[3] = o3 - l;
            }
        }
    }

    // self-reset barrier state for the next graph replay
    __syncthreads();
    if (t == 0) {
        if (atomicAdd(&g_done, 1) == (int)gridDim.x - 1) {
            g_barphase = 0;
            g_done = 0;
        }
    }
}

// ---------------- launch ----------------

extern "C" void kernel_launch(void* const* d_in, const int* in_sizes, int n_in,
                              void* d_out, int out_size) {
    const float* x  = (const float*)d_in[0];
    const int*   ei = (const int*)  d_in[1];
    const float* W1 = (const float*)d_in[2];
    const float* b1 = (const float*)d_in[3];
    const float* W2 = (const float*)d_in[4];
    const float* b2 = (const float*)d_in[5];

    const int n = in_sizes[0] / FIN;
    const int e = in_sizes[1] / 2;
    const int* src = ei;
    const int* dst = ei + e;

    // 148 SMs x 3 CTAs (guaranteed by launch_bounds) -> fully resident grid
    k_fused<<<444, TPB>>>(x, src, dst, e, W1, b1, W2, b2, (float*)d_out, n);
}